// round 8
// baseline (speedup 1.0000x reference)
#include <cuda_runtime.h>
#include <cuda_bf16.h>
#include <cstdint>
#include <cstdio>

#define T_  4096
#define B_  32
#define D_  512
#define H_  256
#define G4_ 1024            // 4*H
#define P_  148             // time-chunks per batch row
#define SPB_ 32             // streams per block
#define NBLK_ ((B_ * P_) / SPB_)   // 148 blocks

// ---------------- scratch (static device globals; no allocations) ----------
__device__ float g_xw[(size_t)B_ * T_ * G4_];   // [b][t][col'] permuted: col'=4*j+q
__device__ float g_Wp[G4_ * D_];                // W_ih rows permuted to col' order (2 MB)
__device__ uint2 g_Wfh[128 * 16 * 32];          // bf16 fragment-packed W_hh (512 KB)
__device__ float g_bb[G4_];                     // b_ih + b_hh (original order)
__device__ int   g_bound[B_][P_ + 1];           // chunk boundaries per batch row

__device__ __forceinline__ float tf32r(float x) {
    float r;
    asm("cvt.rna.tf32.f32 %0, %1;" : "=f"(r) : "f"(x));
    return r;
}

// ---------------- stage 0: chunk boundaries at reset points ----------------
__global__ void k_bounds(const int* __restrict__ reset) {
    int b = blockIdx.x;
    int k = threadIdx.x;
    if (k == 0) {
        g_bound[b][0] = 0;
    } else if (k < P_) {
        int t = (k * T_) / P_;
        while (t < T_ && reset[t * B_ + b] == 0) t++;
        g_bound[b][k] = t;          // either a reset point (state=0) or T
    } else if (k == P_) {
        g_bound[b][P_] = T_;
    }
}

// ---------------- stage 0b: permute W_ih, pack bf16 W_hh frags, biases -----
// permuted col cp <-> original gate row g = (cp&3)*256 + (cp>>2)
__global__ void k_prep(const float* __restrict__ Wih,
                       const float* __restrict__ Whh,
                       const float* __restrict__ bih,
                       const float* __restrict__ bhh) {
    int idx = blockIdx.x * blockDim.x + threadIdx.x;   // grid covers 524288
    if (idx < G4_ * D_) {                              // g_Wp: permuted W_ih copy
        int cp = idx >> 9;
        int d  = idx & 511;
        int g  = ((cp & 3) << 8) + (cp >> 2);
        g_Wp[idx] = Wih[g * D_ + d];
    }
    if (idx < 128 * 16 * 32) {                         // g_Wfh: bf16 B-fragments
        int lane  = idx & 31;
        int kt    = (idx >> 5) & 15;
        int ntile = idx >> 9;
        int gid = lane >> 2, qid = lane & 3;
        int colp = ntile * 8 + gid;
        int g = ((colp & 3) << 8) + (colp >> 2);
        int k0 = kt * 16 + 2 * qid;
        const float* wr = Whh + (size_t)g * H_;
        __nv_bfloat162 lo = { __float2bfloat16(wr[k0]),     __float2bfloat16(wr[k0 + 1]) };
        __nv_bfloat162 hi = { __float2bfloat16(wr[k0 + 8]), __float2bfloat16(wr[k0 + 9]) };
        uint2 v;
        v.x = *(const uint32_t*)&lo;
        v.y = *(const uint32_t*)&hi;
        g_Wfh[idx] = v;
    }
    if (idx < G4_) g_bb[idx] = bih[idx] + bhh[idx];
}

// ---------------- stage 1: xW GEMM via tf32 mma.sync -----------------------
#define GBM 128
#define GBN 128
#define GBK 32
#define BOFF (2 * GBM * GBK)   // Bs offset in dynamic smem (floats)

__device__ __forceinline__ void mma_tf32(float* c, const uint32_t* a, const uint32_t* b) {
    asm volatile(
        "mma.sync.aligned.m16n8k8.row.col.f32.tf32.tf32.f32 "
        "{%0,%1,%2,%3},{%4,%5,%6,%7},{%8,%9},{%0,%1,%2,%3};"
        : "+f"(c[0]), "+f"(c[1]), "+f"(c[2]), "+f"(c[3])
        : "r"(a[0]), "r"(a[1]), "r"(a[2]), "r"(a[3]), "r"(b[0]), "r"(b[1]));
}

__global__ __launch_bounds__(256) void k_gemm_tf32(const float* __restrict__ A) {
    extern __shared__ float sm[];   // As: [2][128][32] swizzled, Bs: same, 64 KB
    __shared__ float bias_sm[GBN];

    const int tid  = threadIdx.x;
    const int warp = tid >> 5;
    const int lane = tid & 31;
    const int wm   = warp >> 1;          // 0..3
    const int wn   = warp & 1;           // 0..1
    const int gid  = lane >> 2;          // groupID 0..7
    const int qid  = lane & 3;           // thread-in-group 0..3
    const int m0   = blockIdx.y * GBM;
    const int n0   = blockIdx.x * GBN;   // permuted col base

    const int crow = tid >> 1;
    const int cc4  = (tid & 1) * 4;
    const float* gA = A    + (size_t)(m0 + crow) * D_ + cc4 * 4;
    const float* gB = g_Wp + (size_t)(n0 + crow) * D_ + cc4 * 4;

    if (tid < GBN) {
        int cp = n0 + tid;
        bias_sm[tid] = g_bb[((cp & 3) << 8) + (cp >> 2)];
    }

    float acc[2][8][4];
#pragma unroll
    for (int i = 0; i < 2; i++)
#pragma unroll
        for (int j = 0; j < 8; j++)
#pragma unroll
            for (int q = 0; q < 4; q++) acc[i][j][q] = 0.f;

    float4 ra[4], rb[4];

#define LOADG(k0)                                                   \
    {                                                               \
        _Pragma("unroll")                                           \
        for (int i = 0; i < 4; i++) {                               \
            ra[i] = *(const float4*)(gA + (k0) + i * 4);            \
            rb[i] = *(const float4*)(gB + (k0) + i * 4);            \
        }                                                           \
    }

#define STORES(buf)                                                             \
    {                                                                           \
        _Pragma("unroll")                                                       \
        for (int i = 0; i < 4; i++) {                                           \
            int sw = ((cc4 + i) ^ (crow & 7)) * 4;                              \
            float4 va;                                                          \
            va.x = tf32r(ra[i].x); va.y = tf32r(ra[i].y);                       \
            va.z = tf32r(ra[i].z); va.w = tf32r(ra[i].w);                       \
            *(float4*)&sm[((buf) * GBM + crow) * GBK + sw] = va;                \
            float4 vb;                                                          \
            vb.x = tf32r(rb[i].x); vb.y = tf32r(rb[i].y);                       \
            vb.z = tf32r(rb[i].z); vb.w = tf32r(rb[i].w);                       \
            *(float4*)&sm[BOFF + ((buf) * GBN + crow) * GBK + sw] = vb;         \
        }                                                                       \
    }

    LOADG(0)
    STORES(0)
    __syncthreads();

    const int NKT = D_ / GBK;   // 16
    for (int kt = 0; kt < NKT; kt++) {
        const int cur = kt & 1;
        if (kt + 1 < NKT) LOADG((kt + 1) * GBK)

#pragma unroll
        for (int kc = 0; kc < 4; kc++) {
            const int k4a = kc * 2;
            uint32_t af[2][4], bf[8][2];
#pragma unroll
            for (int ma = 0; ma < 2; ma++) {
                int rw = wm * 32 + ma * 16 + gid;
                int b0 = (cur * GBM + rw) * GBK;
                int b8 = b0 + 8 * GBK;
                int x  = rw & 7;
                af[ma][0] = __float_as_uint(sm[b0 + ((k4a)     ^ x) * 4 + qid]);
                af[ma][1] = __float_as_uint(sm[b8 + ((k4a)     ^ x) * 4 + qid]);
                af[ma][2] = __float_as_uint(sm[b0 + ((k4a + 1) ^ x) * 4 + qid]);
                af[ma][3] = __float_as_uint(sm[b8 + ((k4a + 1) ^ x) * 4 + qid]);
            }
#pragma unroll
            for (int na = 0; na < 8; na++) {
                int rn = wn * 64 + na * 8 + gid;
                int bb = BOFF + (cur * GBN + rn) * GBK;
                int x  = rn & 7;
                bf[na][0] = __float_as_uint(sm[bb + ((k4a)     ^ x) * 4 + qid]);
                bf[na][1] = __float_as_uint(sm[bb + ((k4a + 1) ^ x) * 4 + qid]);
            }
#pragma unroll
            for (int na = 0; na < 8; na++)
#pragma unroll
                for (int ma = 0; ma < 2; ma++)
                    mma_tf32(acc[ma][na], af[ma], bf[na]);
        }

        if (kt + 1 < NKT) STORES(cur ^ 1)
        __syncthreads();
    }

    // epilogue: +bias, contiguous float2 stores into permuted layout
#pragma unroll
    for (int na = 0; na < 8; na++) {
        const int cl = wn * 64 + na * 8 + qid * 2;
        const float bi0 = bias_sm[cl];
        const float bi1 = bias_sm[cl + 1];
#pragma unroll
        for (int ma = 0; ma < 2; ma++) {
            int m1 = m0 + wm * 32 + ma * 16 + gid;
            int m2 = m1 + 8;
            {
                int t = m1 >> 5, b = m1 & 31;
                float2 v = { acc[ma][na][0] + bi0, acc[ma][na][1] + bi1 };
                *(float2*)(g_xw + ((size_t)b * T_ + t) * G4_ + n0 + cl) = v;
            }
            {
                int t = m2 >> 5, b = m2 & 31;
                float2 v = { acc[ma][na][2] + bi0, acc[ma][na][3] + bi1 };
                *(float2*)(g_xw + ((size_t)b * T_ + t) * G4_ + n0 + cl) = v;
            }
        }
    }
#undef LOADG
#undef STORES
}

// ---------------- stage 2: bf16 tensor-core segment-parallel recurrence ----
__device__ __forceinline__ float sigf(float x) {
    return 1.f / (1.f + __expf(-x));
}

__device__ __forceinline__ void mma_bf16(float* c, const uint32_t* a, const uint32_t* b) {
    asm volatile(
        "mma.sync.aligned.m16n8k16.row.col.f32.bf16.bf16.f32 "
        "{%0,%1,%2,%3},{%4,%5,%6,%7},{%8,%9},{%0,%1,%2,%3};"
        : "+f"(c[0]), "+f"(c[1]), "+f"(c[2]), "+f"(c[3])
        : "r"(a[0]), "r"(a[1]), "r"(a[2]), "r"(a[3]), "r"(b[0]), "r"(b[1]));
}

#define HSTRH 264              // h row stride in halves: 256 + pad 8 (conflict-free)

__global__ __launch_bounds__(512, 1) void k_recur(const int* __restrict__ reset,
                                                  const float* __restrict__ Wp,
                                                  const float* __restrict__ bp,
                                                  float* __restrict__ out) {
    __shared__ __nv_bfloat16 hsb[2][SPB_][HSTRH];   // double-buffered bf16 h
    __shared__ float red[2][SPB_][16];              // double-buffered proj partials
    __shared__ int s_start[SPB_], s_end[SPB_], s_b[SPB_];

    const int tid  = threadIdx.x;
    const int w    = tid >> 5;              // warp 0..15 -> ntiles w*8..w*8+7
    const int lane = tid & 31;
    const int gid  = lane >> 2;
    const int qid  = lane & 3;

    if (tid < SPB_) {
        int sid = blockIdx.x * SPB_ + tid;
        int b = sid / P_;
        int k = sid % P_;
        s_start[tid] = g_bound[b][k];
        s_end[tid]   = g_bound[b][k + 1];
        s_b[tid]     = b;
    }
    {
        uint32_t* hz = (uint32_t*)&hsb[0][0][0];
        for (int q = tid; q < SPB_ * HSTRH / 2; q += 512) hz[q] = 0u;
    }
    __syncthreads();

    // fixed per-thread stream identities: s = mt*16 + gid + 8*(qid&1)
    const int sA = gid + 8 * (qid & 1);
    const int sB = sA + 16;
    const int stA = s_start[sA], enA = s_end[sA], bA = s_b[sA];
    const int stB = s_start[sB], enB = s_end[sB], bB = s_b[sB];

    int maxlen = 0;
    for (int s = 0; s < SPB_; s++) maxlen = max(maxlen, s_end[s] - s_start[s]);

    float wp8[8];
#pragma unroll
    for (int i = 0; i < 8; i++) wp8[i] = Wp[(w * 8 + i) * 2 + (qid >> 1)];
    const float bpv = bp[0];

    float cell[8][2];
#pragma unroll
    for (int i = 0; i < 8; i++) { cell[i][0] = 0.f; cell[i][1] = 0.f; }

    for (int r = 0; r < maxlen; r++) {
        const int rb = r & 1;
        const __nv_bfloat16* hcur = &hsb[rb][0][0];
        __nv_bfloat16*       hnxt = &hsb[rb ^ 1][0][0];

        const int tA = stA + r;
        const int tB = stB + r;
        const bool actA = tA < enA;
        const bool actB = tB < enB;
        float keepA = 0.f, keepB = 0.f;
        const float* xrA = g_xw;
        const float* xrB = g_xw;
        if (actA) {
            keepA = (reset[tA * B_ + bA] != 0) ? 0.f : 1.f;
            xrA = g_xw + ((size_t)bA * T_ + tA) * G4_;
        }
        if (actB) {
            keepB = (reset[tB * B_ + bB] != 0) ? 0.f : 1.f;
            xrB = g_xw + ((size_t)bB * T_ + tB) * G4_;
        }

        float prjA = 0.f, prjB = 0.f;

#pragma unroll
        for (int half = 0; half < 2; half++) {
            float cacc[4][2][4];
#pragma unroll
            for (int nt = 0; nt < 4; nt++)
#pragma unroll
                for (int mt = 0; mt < 2; mt++)
#pragma unroll
                    for (int q = 0; q < 4; q++) cacc[nt][mt][q] = 0.f;

            const int nbase = w * 8 + half * 4;
            uint2 bv[4], bvn[4];
#pragma unroll
            for (int nt = 0; nt < 4; nt++)
                bv[nt] = g_Wfh[((nbase + nt) * 16) * 32 + lane];

            // gate GEMM (bf16 m16n8k16), weights prefetched one k-tile ahead
            for (int kt = 0; kt < 16; kt++) {
                const int ktn = (kt + 1) & 15;
#pragma unroll
                for (int nt = 0; nt < 4; nt++)
                    bvn[nt] = g_Wfh[((nbase + nt) * 16 + ktn) * 32 + lane];

                const int kb = kt * 16 + 2 * qid;
                uint32_t a[2][4];
#pragma unroll
                for (int mt = 0; mt < 2; mt++) {
                    const __nv_bfloat16* hb = hcur + (mt * 16 + gid) * HSTRH;
                    a[mt][0] = *(const uint32_t*)(hb + kb);
                    a[mt][1] = *(const uint32_t*)(hb + 8 * HSTRH + kb);
                    a[mt][2] = *(const uint32_t*)(hb + kb + 8);
                    a[mt][3] = *(const uint32_t*)(hb + 8 * HSTRH + kb + 8);
                }
#pragma unroll
                for (int nt = 0; nt < 4; nt++)
#pragma unroll
                    for (int mt = 0; mt < 2; mt++)
                        mma_bf16(cacc[nt][mt], a[mt], (const uint32_t*)&bv[nt]);
#pragma unroll
                for (int nt = 0; nt < 4; nt++) bv[nt] = bvn[nt];
            }

            // pointwise LSTM for this half's 4 ntiles
#pragma unroll
            for (int nt = 0; nt < 4; nt++) {
                const int ni = half * 4 + nt;
                const int j  = (w * 8 + ni) * 2 + (qid >> 1);
#pragma unroll
                for (int mt = 0; mt < 2; mt++) {
                    float* C = cacc[nt][mt];
                    float sx = (qid & 1) ? C[0] : C[2];
                    float sy = (qid & 1) ? C[1] : C[3];
                    float rx = __shfl_xor_sync(0xffffffffu, sx, 1);
                    float ry = __shfl_xor_sync(0xffffffffu, sy, 1);
                    float gi, gf, gg, go;
                    if (qid & 1) { gi = rx;   gf = ry;   gg = C[2]; go = C[3]; }
                    else         { gi = C[0]; gf = C[1]; gg = rx;   go = ry;  }

                    const bool  act  = mt ? actB : actA;
                    const float keep = mt ? keepB : keepA;
                    const float* xr  = mt ? xrB : xrA;
                    float hh = 0.f;
                    if (act) {
                        float4 xv = *(const float4*)(xr + 4 * j);
                        float vi = xv.x + keep * gi;
                        float vf = xv.y + keep * gf;
                        float vg = xv.z + keep * gg;
                        float vo = xv.w + keep * go;
                        float cc = sigf(vf) * (cell[ni][mt] * keep) + sigf(vi) * tanhf(vg);
                        hh = sigf(vo) * tanhf(cc);
                        cell[ni][mt] = cc;
                        if (mt) prjB += wp8[ni] * hh;
                        else    prjA += wp8[ni] * hh;
                    }
                    const int s = mt ? sB : sA;
                    hnxt[s * HSTRH + j] = __float2bfloat16(hh);
                }
            }
        }

        // projection partials (qid ^ 2 shares the same stream)
        prjA += __shfl_xor_sync(0xffffffffu, prjA, 2);
        prjB += __shfl_xor_sync(0xffffffffu, prjB, 2);
        if (qid < 2) {
            red[rb][sA][w] = prjA;
            red[rb][sB][w] = prjB;
        }
        __syncthreads();

        if (tid < SPB_) {
            int t = s_start[tid] + r;
            if (t < s_end[tid]) {
                float sum = bpv;
#pragma unroll
                for (int i = 0; i < 16; i++) sum += red[rb][tid][i];
                out[t * B_ + s_b[tid]] = sum;
            }
        }
        // no trailing sync: red is double-buffered by rb, h by rb^1
    }
}

// ---------------- launch ----------------------------------------------------
extern "C" void kernel_launch(void* const* d_in, const int* in_sizes, int n_in,
                              void* d_out, int out_size) {
    const float* x     = (const float*)d_in[0];
    const int*   reset = (const int*)  d_in[1];
    const float* Wih   = (const float*)d_in[2];
    const float* Whh   = (const float*)d_in[3];
    const float* bih   = (const float*)d_in[4];
    const float* bhh   = (const float*)d_in[5];
    const float* Wp    = (const float*)d_in[6];
    const float* bp    = (const float*)d_in[7];
    float* out = (float*)d_out;

    static int attr_set = 0;
    if (!attr_set) {
        cudaFuncSetAttribute(k_gemm_tf32,
                             cudaFuncAttributeMaxDynamicSharedMemorySize, 65536);
        attr_set = 1;
    }

    k_bounds<<<B_, 160>>>(reset);
    k_prep<<<2048, 256>>>(Wih, Whh, bih, bhh);

    dim3 grid(G4_ / GBN, (T_ * B_) / GBM);
    k_gemm_tf32<<<grid, 256, 65536>>>(x);

    k_recur<<<NBLK_, 512>>>(reset, Wp, bp, out);
}

// round 9
// speedup vs baseline: 1.2667x; 1.2667x over previous
#include <cuda_runtime.h>
#include <cuda_bf16.h>
#include <cstdint>
#include <cstdio>

#define T_  4096
#define B_  32
#define D_  512
#define H_  256
#define G4_ 1024            // 4*H
#define P_  296             // time-chunks per batch row
#define SPB_ 64             // streams per block
#define NBLK_ ((B_ * P_) / SPB_)   // 148 blocks

// ---------------- scratch (static device globals; no allocations) ----------
__device__ float g_xw[(size_t)B_ * T_ * G4_];   // [b][t][col'] permuted: col'=4*j+q
__device__ uint2 g_Wfh[128 * 16 * 32];          // bf16 fragment-packed W_hh (512 KB)
__device__ float g_bb[G4_];                     // b_ih + b_hh (original order)
__device__ int   g_bound[B_][P_ + 1];           // chunk boundaries per batch row

__device__ __forceinline__ float tf32r(float x) {
    float r;
    asm("cvt.rna.tf32.f32 %0, %1;" : "=f"(r) : "f"(x));
    return r;
}

// ---------------- stage 0: chunk boundaries at reset points ----------------
__global__ void k_bounds(const int* __restrict__ reset) {
    int b = blockIdx.x;
    int k = threadIdx.x;
    if (k == 0) {
        g_bound[b][0] = 0;
    } else if (k < P_) {
        int t = (k * T_) / P_;
        while (t < T_ && reset[t * B_ + b] == 0) t++;
        g_bound[b][k] = t;          // either a reset point (state=0) or T
    } else if (k == P_) {
        g_bound[b][P_] = T_;
    }
}

// ---------------- stage 0b: pack bf16 W_hh frags + fuse biases -------------
// permuted col cp <-> original gate row g = (cp&3)*256 + (cp>>2)
__global__ void k_prep(const float* __restrict__ Whh,
                       const float* __restrict__ bih,
                       const float* __restrict__ bhh) {
    int idx = blockIdx.x * blockDim.x + threadIdx.x;   // 65536 threads
    if (idx < 128 * 16 * 32) {                         // g_Wfh: bf16 B-fragments
        int lane  = idx & 31;
        int kt    = (idx >> 5) & 15;
        int ntile = idx >> 9;
        int gid = lane >> 2, qid = lane & 3;
        int colp = ntile * 8 + gid;
        int g = ((colp & 3) << 8) + (colp >> 2);
        int k0 = kt * 16 + 2 * qid;
        const float* wr = Whh + (size_t)g * H_;
        __nv_bfloat162 lo = { __float2bfloat16(wr[k0]),     __float2bfloat16(wr[k0 + 1]) };
        __nv_bfloat162 hi = { __float2bfloat16(wr[k0 + 8]), __float2bfloat16(wr[k0 + 9]) };
        uint2 v;
        v.x = *(const uint32_t*)&lo;
        v.y = *(const uint32_t*)&hi;
        g_Wfh[idx] = v;
    }
    if (idx < G4_) g_bb[idx] = bih[idx] + bhh[idx];
}

// ---------------- stage 1: xW GEMM via tf32 mma.sync (round-6 version) -----
#define GBM 128
#define GBN 128
#define GBK 32
#define BOFF (2 * GBM * GBK)   // Bs offset in dynamic smem (floats)

__device__ __forceinline__ void mma_tf32(float* c, const uint32_t* a, const uint32_t* b) {
    asm volatile(
        "mma.sync.aligned.m16n8k8.row.col.f32.tf32.tf32.f32 "
        "{%0,%1,%2,%3},{%4,%5,%6,%7},{%8,%9},{%0,%1,%2,%3};"
        : "+f"(c[0]), "+f"(c[1]), "+f"(c[2]), "+f"(c[3])
        : "r"(a[0]), "r"(a[1]), "r"(a[2]), "r"(a[3]), "r"(b[0]), "r"(b[1]));
}

__global__ __launch_bounds__(256) void k_gemm_tf32(const float* __restrict__ A,
                                                   const float* __restrict__ Bw) {
    extern __shared__ float sm[];   // As: [2][128][32] swizzled, Bs: same, 64 KB

    const int tid  = threadIdx.x;
    const int warp = tid >> 5;
    const int lane = tid & 31;
    const int wm   = warp >> 1;          // 0..3
    const int wn   = warp & 1;           // 0..1
    const int gid  = lane >> 2;          // groupID 0..7
    const int qid  = lane & 3;           // thread-in-group 0..3
    const int m0   = blockIdx.y * GBM;
    const int n0   = blockIdx.x * GBN;

    const int crow = tid >> 1;
    const int cc4  = (tid & 1) * 4;
    const float* gA = A  + (size_t)(m0 + crow) * D_ + cc4 * 4;
    const float* gB = Bw + (size_t)(n0 + crow) * D_ + cc4 * 4;

    float acc[2][8][4];
#pragma unroll
    for (int i = 0; i < 2; i++)
#pragma unroll
        for (int j = 0; j < 8; j++)
#pragma unroll
            for (int q = 0; q < 4; q++) acc[i][j][q] = 0.f;

    float4 ra[4], rb[4];

#define LOADG(k0)                                                   \
    {                                                               \
        _Pragma("unroll")                                           \
        for (int i = 0; i < 4; i++) {                               \
            ra[i] = *(const float4*)(gA + (k0) + i * 4);            \
            rb[i] = *(const float4*)(gB + (k0) + i * 4);            \
        }                                                           \
    }

#define STORES(buf)                                                             \
    {                                                                           \
        _Pragma("unroll")                                                       \
        for (int i = 0; i < 4; i++) {                                           \
            int sw = ((cc4 + i) ^ (crow & 7)) * 4;                              \
            float4 va;                                                          \
            va.x = tf32r(ra[i].x); va.y = tf32r(ra[i].y);                       \
            va.z = tf32r(ra[i].z); va.w = tf32r(ra[i].w);                       \
            *(float4*)&sm[((buf) * GBM + crow) * GBK + sw] = va;                \
            float4 vb;                                                          \
            vb.x = tf32r(rb[i].x); vb.y = tf32r(rb[i].y);                       \
            vb.z = tf32r(rb[i].z); vb.w = tf32r(rb[i].w);                       \
            *(float4*)&sm[BOFF + ((buf) * GBN + crow) * GBK + sw] = vb;         \
        }                                                                       \
    }

    LOADG(0)
    STORES(0)
    __syncthreads();

    const int NKT = D_ / GBK;   // 16
    for (int kt = 0; kt < NKT; kt++) {
        const int cur = kt & 1;
        if (kt + 1 < NKT) LOADG((kt + 1) * GBK)

#pragma unroll
        for (int kc = 0; kc < 4; kc++) {
            const int k4a = kc * 2;
            uint32_t af[2][4], bf[8][2];
#pragma unroll
            for (int ma = 0; ma < 2; ma++) {
                int rw = wm * 32 + ma * 16 + gid;
                int b0 = (cur * GBM + rw) * GBK;
                int b8 = b0 + 8 * GBK;
                int x  = rw & 7;
                af[ma][0] = __float_as_uint(sm[b0 + ((k4a)     ^ x) * 4 + qid]);
                af[ma][1] = __float_as_uint(sm[b8 + ((k4a)     ^ x) * 4 + qid]);
                af[ma][2] = __float_as_uint(sm[b0 + ((k4a + 1) ^ x) * 4 + qid]);
                af[ma][3] = __float_as_uint(sm[b8 + ((k4a + 1) ^ x) * 4 + qid]);
            }
#pragma unroll
            for (int na = 0; na < 8; na++) {
                int rn = wn * 64 + na * 8 + gid;
                int bb = BOFF + (cur * GBN + rn) * GBK;
                int x  = rn & 7;
                bf[na][0] = __float_as_uint(sm[bb + ((k4a)     ^ x) * 4 + qid]);
                bf[na][1] = __float_as_uint(sm[bb + ((k4a + 1) ^ x) * 4 + qid]);
            }
#pragma unroll
            for (int na = 0; na < 8; na++)
#pragma unroll
                for (int ma = 0; ma < 2; ma++)
                    mma_tf32(acc[ma][na], af[ma], bf[na]);
        }

        if (kt + 1 < NKT) STORES(cur ^ 1)
        __syncthreads();
    }

    // epilogue: +bias, scatter to PERMUTED cols: n -> 4*(n&255) + (n>>8)
#pragma unroll
    for (int na = 0; na < 8; na++) {
        const int n = n0 + wn * 64 + na * 8 + qid * 2;
        const float bi0 = g_bb[n];
        const float bi1 = g_bb[n + 1];
        const int cp0 = 4 * (n & 255) + (n >> 8);
        const int cp1 = cp0 + 4;
#pragma unroll
        for (int ma = 0; ma < 2; ma++) {
            int m1 = m0 + wm * 32 + ma * 16 + gid;
            int m2 = m1 + 8;
            {
                int t = m1 >> 5, b = m1 & 31;
                float* dst = g_xw + ((size_t)b * T_ + t) * G4_;
                dst[cp0] = acc[ma][na][0] + bi0;
                dst[cp1] = acc[ma][na][1] + bi1;
            }
            {
                int t = m2 >> 5, b = m2 & 31;
                float* dst = g_xw + ((size_t)b * T_ + t) * G4_;
                dst[cp0] = acc[ma][na][2] + bi0;
                dst[cp1] = acc[ma][na][3] + bi1;
            }
        }
    }
#undef LOADG
#undef STORES
}

// ---------------- stage 2: bf16 recurrence, 64 streams per block -----------
__device__ __forceinline__ float sigf(float x) {
    return 1.f / (1.f + __expf(-x));
}

__device__ __forceinline__ void mma_bf16(float* c, const uint32_t* a, const uint32_t* b) {
    asm volatile(
        "mma.sync.aligned.m16n8k16.row.col.f32.bf16.bf16.f32 "
        "{%0,%1,%2,%3},{%4,%5,%6,%7},{%8,%9},{%0,%1,%2,%3};"
        : "+f"(c[0]), "+f"(c[1]), "+f"(c[2]), "+f"(c[3])
        : "r"(a[0]), "r"(a[1]), "r"(a[2]), "r"(a[3]), "r"(b[0]), "r"(b[1]));
}

#define HSTRH 264              // h row stride in halves: 256 + pad 8
#define HBUFH (SPB_ * HSTRH)   // halves per h buffer

__global__ __launch_bounds__(512, 1) void k_recur(const int* __restrict__ reset,
                                                  const float* __restrict__ Wp,
                                                  const float* __restrict__ bp,
                                                  float* __restrict__ out) {
    extern __shared__ char smr[];
    __nv_bfloat16* hsb = (__nv_bfloat16*)smr;              // [2][64][264] bf16
    float* red = (float*)(smr + 2 * HBUFH * 2);            // [2][64][16]
    int*   meta = (int*)(red + 2 * SPB_ * 16);
    int* s_start = meta;
    int* s_end   = meta + SPB_;
    int* s_b     = meta + 2 * SPB_;

    const int tid  = threadIdx.x;
    const int w    = tid >> 5;              // warp 0..15 -> ntiles w*8..w*8+7
    const int lane = tid & 31;
    const int gid  = lane >> 2;
    const int qid  = lane & 3;

    if (tid < SPB_) {
        int sid = blockIdx.x * SPB_ + tid;
        int b = sid / P_;
        int k = sid % P_;
        s_start[tid] = g_bound[b][k];
        s_end[tid]   = g_bound[b][k + 1];
        s_b[tid]     = b;
    }
    {
        uint32_t* hz = (uint32_t*)hsb;
        for (int q = tid; q < HBUFH / 2; q += 512) hz[q] = 0u;   // zero buffer 0
    }
    __syncthreads();

    const int sb0 = gid + 8 * (qid & 1);    // stream base within 16

    int maxlen = 0;
    for (int s = 0; s < SPB_; s++) maxlen = max(maxlen, s_end[s] - s_start[s]);

    float wp8[8];
#pragma unroll
    for (int i = 0; i < 8; i++) wp8[i] = Wp[(w * 8 + i) * 2 + (qid >> 1)];
    const float bpv = bp[0];

    float cell[8][4];
#pragma unroll
    for (int i = 0; i < 8; i++)
#pragma unroll
        for (int m = 0; m < 4; m++) cell[i][m] = 0.f;

    for (int r = 0; r < maxlen; r++) {
        const int rb = r & 1;
        const __nv_bfloat16* hcur = hsb + rb * HBUFH;
        __nv_bfloat16*       hnxt = hsb + (rb ^ 1) * HBUFH;

        // per-step state for this thread's 4 streams
        bool  act[4];
        float keep[4];
        const float* xr[4];
#pragma unroll
        for (int mt = 0; mt < 4; mt++) {
            const int s = mt * 16 + sb0;
            const int t = s_start[s] + r;
            act[mt] = t < s_end[s];
            if (act[mt]) {
                const int b = s_b[s];
                keep[mt] = (reset[t * B_ + b] != 0) ? 0.f : 1.f;
                xr[mt] = g_xw + ((size_t)b * T_ + t) * G4_;
            } else {
                keep[mt] = 0.f;
                xr[mt] = g_xw;
            }
        }
        float prj[4] = {0.f, 0.f, 0.f, 0.f};

#pragma unroll
        for (int q4 = 0; q4 < 4; q4++) {
            float cacc[2][4][4];
#pragma unroll
            for (int nt = 0; nt < 2; nt++)
#pragma unroll
                for (int mt = 0; mt < 4; mt++)
#pragma unroll
                    for (int q = 0; q < 4; q++) cacc[nt][mt][q] = 0.f;

            const int nbase = w * 8 + q4 * 2;
            uint2 bv[2], bvn[2];
#pragma unroll
            for (int nt = 0; nt < 2; nt++)
                bv[nt] = g_Wfh[((nbase + nt) * 16) * 32 + lane];

            for (int kt = 0; kt < 16; kt++) {
                const int ktn = (kt + 1) & 15;
#pragma unroll
                for (int nt = 0; nt < 2; nt++)
                    bvn[nt] = g_Wfh[((nbase + nt) * 16 + ktn) * 32 + lane];

                const int kb = kt * 16 + 2 * qid;
                uint32_t a[4][4];
#pragma unroll
                for (int mt = 0; mt < 4; mt++) {
                    const __nv_bfloat16* hb = hcur + (mt * 16 + gid) * HSTRH;
                    a[mt][0] = *(const uint32_t*)(hb + kb);
                    a[mt][1] = *(const uint32_t*)(hb + 8 * HSTRH + kb);
                    a[mt][2] = *(const uint32_t*)(hb + kb + 8);
                    a[mt][3] = *(const uint32_t*)(hb + 8 * HSTRH + kb + 8);
                }
#pragma unroll
                for (int nt = 0; nt < 2; nt++)
#pragma unroll
                    for (int mt = 0; mt < 4; mt++)
                        mma_bf16(cacc[nt][mt], a[mt], (const uint32_t*)&bv[nt]);
#pragma unroll
                for (int nt = 0; nt < 2; nt++) bv[nt] = bvn[nt];
            }

            // pointwise LSTM for this quarter's 2 ntiles x 4 m-tiles
#pragma unroll
            for (int nt = 0; nt < 2; nt++) {
                const int ni = q4 * 2 + nt;
                const int j  = (w * 8 + ni) * 2 + (qid >> 1);
#pragma unroll
                for (int mt = 0; mt < 4; mt++) {
                    float* C = cacc[nt][mt];
                    float sx = (qid & 1) ? C[0] : C[2];
                    float sy = (qid & 1) ? C[1] : C[3];
                    float rx = __shfl_xor_sync(0xffffffffu, sx, 1);
                    float ry = __shfl_xor_sync(0xffffffffu, sy, 1);
                    float gi, gf, gg, go;
                    if (qid & 1) { gi = rx;   gf = ry;   gg = C[2]; go = C[3]; }
                    else         { gi = C[0]; gf = C[1]; gg = rx;   go = ry;  }

                    float hh = 0.f;
                    if (act[mt]) {
                        float4 xv = *(const float4*)(xr[mt] + 4 * j);
                        float vi = xv.x + keep[mt] * gi;
                        float vf = xv.y + keep[mt] * gf;
                        float vg = xv.z + keep[mt] * gg;
                        float vo = xv.w + keep[mt] * go;
                        float cc = sigf(vf) * (cell[ni][mt] * keep[mt]) + sigf(vi) * tanhf(vg);
                        hh = sigf(vo) * tanhf(cc);
                        cell[ni][mt] = cc;
                        prj[mt] += wp8[ni] * hh;
                    }
                    hnxt[(mt * 16 + sb0) * HSTRH + j] = __float2bfloat16(hh);
                }
            }
        }

        // projection partials (qid ^ 2 shares the same stream)
#pragma unroll
        for (int mt = 0; mt < 4; mt++)
            prj[mt] += __shfl_xor_sync(0xffffffffu, prj[mt], 2);
        if (qid < 2) {
#pragma unroll
            for (int mt = 0; mt < 4; mt++)
                red[(size_t)rb * SPB_ * 16 + (mt * 16 + sb0) * 16 + w] = prj[mt];
        }
        __syncthreads();

        if (tid < SPB_) {
            int t = s_start[tid] + r;
            if (t < s_end[tid]) {
                float sum = bpv;
#pragma unroll
                for (int i = 0; i < 16; i++)
                    sum += red[(size_t)rb * SPB_ * 16 + tid * 16 + i];
                out[t * B_ + s_b[tid]] = sum;
            }
        }
        // no trailing sync: red double-buffered by rb, h by rb^1
    }
}

// ---------------- launch ----------------------------------------------------
extern "C" void kernel_launch(void* const* d_in, const int* in_sizes, int n_in,
                              void* d_out, int out_size) {
    const float* x     = (const float*)d_in[0];
    const int*   reset = (const int*)  d_in[1];
    const float* Wih   = (const float*)d_in[2];
    const float* Whh   = (const float*)d_in[3];
    const float* bih   = (const float*)d_in[4];
    const float* bhh   = (const float*)d_in[5];
    const float* Wp    = (const float*)d_in[6];
    const float* bp    = (const float*)d_in[7];
    float* out = (float*)d_out;

    const int rsm = 2 * HBUFH * 2 + 2 * SPB_ * 16 * 4 + 3 * SPB_ * 4 + 128;
    static int attr_set = 0;
    if (!attr_set) {
        cudaFuncSetAttribute(k_gemm_tf32,
                             cudaFuncAttributeMaxDynamicSharedMemorySize, 65536);
        cudaFuncSetAttribute(k_recur,
                             cudaFuncAttributeMaxDynamicSharedMemorySize, rsm);
        attr_set = 1;
    }

    k_bounds<<<B_, 320>>>(reset);
    k_prep<<<256, 256>>>(Whh, bih, bhh);

    dim3 grid(G4_ / GBN, (T_ * B_) / GBM);
    k_gemm_tf32<<<grid, 256, 65536>>>(x, Wih);

    k_recur<<<NBLK_, 512, rsm>>>(reset, Wp, bp, out);
}

// round 12
// speedup vs baseline: 1.4453x; 1.1410x over previous
#include <cuda_runtime.h>
#include <cuda_bf16.h>
#include <cuda_fp16.h>
#include <cstdint>
#include <cstdio>

#define T_  4096
#define B_  32
#define D_  512
#define H_  256
#define G4_ 1024            // 4*H
#define P_  296             // time-chunks per batch row
#define SPB_ 64             // streams per block
#define NBLK_ ((B_ * P_) / SPB_)   // 148 blocks

// ---------------- scratch (static device globals; no allocations) ----------
__device__ __half g_xwh[(size_t)B_ * T_ * G4_]; // [b][t][col'] fp16, col'=4*j+q (256 MB)
__device__ float g_Wp[G4_ * D_];                // W_ih rows permuted to col' order (2 MB)
__device__ uint2 g_Wfh[128 * 16 * 32];          // bf16 fragment-packed W_hh (512 KB)
__device__ float g_bb[G4_];                     // b_ih + b_hh (original order)
__device__ int   g_bound[B_][P_ + 1];           // chunk boundaries per batch row

__device__ __forceinline__ float tf32r(float x) {
    float r;
    asm("cvt.rna.tf32.f32 %0, %1;" : "=f"(r) : "f"(x));
    return r;
}

// ---------------- stage 0: chunk boundaries at reset points ----------------
__global__ void k_bounds(const int* __restrict__ reset) {
    int b = blockIdx.x;
    int k = threadIdx.x;
    if (k == 0) {
        g_bound[b][0] = 0;
    } else if (k < P_) {
        int t = (k * T_) / P_;
        while (t < T_ && reset[t * B_ + b] == 0) t++;
        g_bound[b][k] = t;          // either a reset point (state=0) or T
    } else if (k == P_) {
        g_bound[b][P_] = T_;
    }
}

// ---------------- stage 0b: permute W_ih, pack bf16 W_hh frags, biases -----
// permuted col cp <-> original gate row g = (cp&3)*256 + (cp>>2)
__global__ void k_prep(const float* __restrict__ Wih,
                       const float* __restrict__ Whh,
                       const float* __restrict__ bih,
                       const float* __restrict__ bhh) {
    int idx = blockIdx.x * blockDim.x + threadIdx.x;   // grid covers 524288
    if (idx < G4_ * D_) {                              // g_Wp: permuted W_ih copy
        int cp = idx >> 9;
        int d  = idx & 511;
        int g  = ((cp & 3) << 8) + (cp >> 2);
        g_Wp[idx] = Wih[g * D_ + d];
    }
    if (idx < 128 * 16 * 32) {                         // g_Wfh: bf16 B-fragments
        int lane  = idx & 31;
        int kt    = (idx >> 5) & 15;
        int ntile = idx >> 9;
        int gid = lane >> 2, qid = lane & 3;
        int colp = ntile * 8 + gid;
        int g = ((colp & 3) << 8) + (colp >> 2);
        int k0 = kt * 16 + 2 * qid;
        const float* wr = Whh + (size_t)g * H_;
        __nv_bfloat162 lo = { __float2bfloat16(wr[k0]),     __float2bfloat16(wr[k0 + 1]) };
        __nv_bfloat162 hi = { __float2bfloat16(wr[k0 + 8]), __float2bfloat16(wr[k0 + 9]) };
        uint2 v;
        v.x = *(const uint32_t*)&lo;
        v.y = *(const uint32_t*)&hi;
        g_Wfh[idx] = v;
    }
    if (idx < G4_) g_bb[idx] = bih[idx] + bhh[idx];
}

// ---------------- stage 1: xW GEMM via tf32 mma.sync, permuted-N -----------
#define GBM 128
#define GBN 128
#define GBK 32
#define BOFF (2 * GBM * GBK)   // Bs offset in dynamic smem (floats)

__device__ __forceinline__ void mma_tf32(float* c, const uint32_t* a, const uint32_t* b) {
    asm volatile(
        "mma.sync.aligned.m16n8k8.row.col.f32.tf32.tf32.f32 "
        "{%0,%1,%2,%3},{%4,%5,%6,%7},{%8,%9},{%0,%1,%2,%3};"
        : "+f"(c[0]), "+f"(c[1]), "+f"(c[2]), "+f"(c[3])
        : "r"(a[0]), "r"(a[1]), "r"(a[2]), "r"(a[3]), "r"(b[0]), "r"(b[1]));
}

__global__ __launch_bounds__(256) void k_gemm_tf32(const float* __restrict__ A) {
    extern __shared__ float sm[];   // As: [2][128][32] swizzled, Bs: same, 64 KB
    __shared__ float bias_sm[GBN];

    const int tid  = threadIdx.x;
    const int warp = tid >> 5;
    const int lane = tid & 31;
    const int wm   = warp >> 1;          // 0..3
    const int wn   = warp & 1;           // 0..1
    const int gid  = lane >> 2;          // groupID 0..7
    const int qid  = lane & 3;           // thread-in-group 0..3
    const int m0   = blockIdx.y * GBM;
    const int n0   = blockIdx.x * GBN;   // permuted col base

    const int crow = tid >> 1;
    const int cc4  = (tid & 1) * 4;
    const float* gA = A    + (size_t)(m0 + crow) * D_ + cc4 * 4;
    const float* gB = g_Wp + (size_t)(n0 + crow) * D_ + cc4 * 4;

    if (tid < GBN) {
        int cp = n0 + tid;
        bias_sm[tid] = g_bb[((cp & 3) << 8) + (cp >> 2)];
    }

    float acc[2][8][4];
#pragma unroll
    for (int i = 0; i < 2; i++)
#pragma unroll
        for (int j = 0; j < 8; j++)
#pragma unroll
            for (int q = 0; q < 4; q++) acc[i][j][q] = 0.f;

    float4 ra[4], rb[4];

#define LOADG(k0)                                                   \
    {                                                               \
        _Pragma("unroll")                                           \
        for (int i = 0; i < 4; i++) {                               \
            ra[i] = *(const float4*)(gA + (k0) + i * 4);            \
            rb[i] = *(const float4*)(gB + (k0) + i * 4);            \
        }                                                           \
    }

#define STORES(buf)                                                             \
    {                                                                           \
        _Pragma("unroll")                                                       \
        for (int i = 0; i < 4; i++) {                                           \
            int sw = ((cc4 + i) ^ (crow & 7)) * 4;                              \
            float4 va;                                                          \
            va.x = tf32r(ra[i].x); va.y = tf32r(ra[i].y);                       \
            va.z = tf32r(ra[i].z); va.w = tf32r(ra[i].w);                       \
            *(float4*)&sm[((buf) * GBM + crow) * GBK + sw] = va;                \
            float4 vb;                                                          \
            vb.x = tf32r(rb[i].x); vb.y = tf32r(rb[i].y);                       \
            vb.z = tf32r(rb[i].z); vb.w = tf32r(rb[i].w);                       \
            *(float4*)&sm[BOFF + ((buf) * GBN + crow) * GBK + sw] = vb;         \
        }                                                                       \
    }

    LOADG(0)
    STORES(0)
    __syncthreads();

    const int NKT = D_ / GBK;   // 16
    for (int kt = 0; kt < NKT; kt++) {
        const int cur = kt & 1;
        if (kt + 1 < NKT) LOADG((kt + 1) * GBK)

#pragma unroll
        for (int kc = 0; kc < 4; kc++) {
            const int k4a = kc * 2;
            uint32_t af[2][4], bf[8][2];
#pragma unroll
            for (int ma = 0; ma < 2; ma++) {
                int rw = wm * 32 + ma * 16 + gid;
                int b0 = (cur * GBM + rw) * GBK;
                int b8 = b0 + 8 * GBK;
                int x  = rw & 7;
                af[ma][0] = __float_as_uint(sm[b0 + ((k4a)     ^ x) * 4 + qid]);
                af[ma][1] = __float_as_uint(sm[b8 + ((k4a)     ^ x) * 4 + qid]);
                af[ma][2] = __float_as_uint(sm[b0 + ((k4a + 1) ^ x) * 4 + qid]);
                af[ma][3] = __float_as_uint(sm[b8 + ((k4a + 1) ^ x) * 4 + qid]);
            }
#pragma unroll
            for (int na = 0; na < 8; na++) {
                int rn = wn * 64 + na * 8 + gid;
                int bb = BOFF + (cur * GBN + rn) * GBK;
                int x  = rn & 7;
                bf[na][0] = __float_as_uint(sm[bb + ((k4a)     ^ x) * 4 + qid]);
                bf[na][1] = __float_as_uint(sm[bb + ((k4a + 1) ^ x) * 4 + qid]);
            }
#pragma unroll
            for (int na = 0; na < 8; na++)
#pragma unroll
                for (int ma = 0; ma < 2; ma++)
                    mma_tf32(acc[ma][na], af[ma], bf[na]);
        }

        if (kt + 1 < NKT) STORES(cur ^ 1)
        __syncthreads();
    }

    // epilogue: +bias, contiguous half2 stores into permuted fp16 layout
#pragma unroll
    for (int na = 0; na < 8; na++) {
        const int cl = wn * 64 + na * 8 + qid * 2;
        const float bi0 = bias_sm[cl];
        const float bi1 = bias_sm[cl + 1];
#pragma unroll
        for (int ma = 0; ma < 2; ma++) {
            int m1 = m0 + wm * 32 + ma * 16 + gid;
            int m2 = m1 + 8;
            {
                int t = m1 >> 5, b = m1 & 31;
                __half2 v = __floats2half2_rn(acc[ma][na][0] + bi0, acc[ma][na][1] + bi1);
                *(__half2*)(g_xwh + ((size_t)b * T_ + t) * G4_ + n0 + cl) = v;
            }
            {
                int t = m2 >> 5, b = m2 & 31;
                __half2 v = __floats2half2_rn(acc[ma][na][2] + bi0, acc[ma][na][3] + bi1);
                *(__half2*)(g_xwh + ((size_t)b * T_ + t) * G4_ + n0 + cl) = v;
            }
        }
    }
#undef LOADG
#undef STORES
}

// ---------------- stage 2: bf16 recurrence, 64 streams per block -----------
__device__ __forceinline__ float sigf(float x) {
    return 1.f / (1.f + __expf(-x));
}

__device__ __forceinline__ void mma_bf16(float* c, const uint32_t* a, const uint32_t* b) {
    asm volatile(
        "mma.sync.aligned.m16n8k16.row.col.f32.bf16.bf16.f32 "
        "{%0,%1,%2,%3},{%4,%5,%6,%7},{%8,%9},{%0,%1,%2,%3};"
        : "+f"(c[0]), "+f"(c[1]), "+f"(c[2]), "+f"(c[3])
        : "r"(a[0]), "r"(a[1]), "r"(a[2]), "r"(a[3]), "r"(b[0]), "r"(b[1]));
}

#define HSTRH 264              // h row stride in halves: 256 + pad 8
#define HBUFH (SPB_ * HSTRH)   // halves per h buffer

__global__ __launch_bounds__(512, 1) void k_recur(const int* __restrict__ reset,
                                                  const float* __restrict__ Wp,
                                                  const float* __restrict__ bp,
                                                  float* __restrict__ out) {
    extern __shared__ char smr[];
    __nv_bfloat16* hsb = (__nv_bfloat16*)smr;              // [2][64][264] bf16
    float* red = (float*)(smr + 2 * HBUFH * 2);            // [2][64][16]
    int*   meta = (int*)(red + 2 * SPB_ * 16);
    int* s_start = meta;
    int* s_end   = meta + SPB_;
    int* s_b     = meta + 2 * SPB_;

    const int tid  = threadIdx.x;
    const int w    = tid >> 5;              // warp 0..15 -> ntiles w*8..w*8+7
    const int lane = tid & 31;
    const int gid  = lane >> 2;
    const int qid  = lane & 3;

    if (tid < SPB_) {
        int sid = blockIdx.x * SPB_ + tid;
        int b = sid / P_;
        int k = sid % P_;
        s_start[tid] = g_bound[b][k];
        s_end[tid]   = g_bound[b][k + 1];
        s_b[tid]     = b;
    }
    {
        uint32_t* hz = (uint32_t*)hsb;
        for (int q = tid; q < HBUFH / 2; q += 512) hz[q] = 0u;   // zero buffer 0
    }
    __syncthreads();

    const int sb0 = gid + 8 * (qid & 1);    // stream base within 16

    int maxlen = 0;
    for (int s = 0; s < SPB_; s++) maxlen = max(maxlen, s_end[s] - s_start[s]);

    float wp8[8];
#pragma unroll
    for (int i = 0; i < 8; i++) wp8[i] = Wp[(w * 8 + i) * 2 + (qid >> 1)];
    const float bpv = bp[0];

    float cell[8][4];
#pragma unroll
    for (int i = 0; i < 8; i++)
#pragma unroll
        for (int m = 0; m < 4; m++) cell[i][m] = 0.f;

    for (int r = 0; r < maxlen; r++) {
        const int rb = r & 1;
        const __nv_bfloat16* hcur = hsb + rb * HBUFH;
        __nv_bfloat16*       hnxt = hsb + (rb ^ 1) * HBUFH;

        // per-step state for this thread's 4 streams
        bool  act[4];
        float keep[4];
        const __half* xr[4];
#pragma unroll
        for (int mt = 0; mt < 4; mt++) {
            const int s = mt * 16 + sb0;
            const int t = s_start[s] + r;
            act[mt] = t < s_end[s];
            if (act[mt]) {
                const int b = s_b[s];
                keep[mt] = (reset[t * B_ + b] != 0) ? 0.f : 1.f;
                xr[mt] = g_xwh + ((size_t)b * T_ + t) * G4_;
            } else {
                keep[mt] = 0.f;
                xr[mt] = g_xwh;
            }
        }
        float prj[4] = {0.f, 0.f, 0.f, 0.f};

#pragma unroll
        for (int q4 = 0; q4 < 4; q4++) {
            float cacc[2][4][4];
#pragma unroll
            for (int nt = 0; nt < 2; nt++)
#pragma unroll
                for (int mt = 0; mt < 4; mt++)
#pragma unroll
                    for (int q = 0; q < 4; q++) cacc[nt][mt][q] = 0.f;

            const int nbase = w * 8 + q4 * 2;
            uint2 bv[2], bvn[2];
#pragma unroll
            for (int nt = 0; nt < 2; nt++)
                bv[nt] = g_Wfh[((nbase + nt) * 16) * 32 + lane];

            for (int kt = 0; kt < 16; kt++) {
                const int ktn = (kt + 1) & 15;
#pragma unroll
                for (int nt = 0; nt < 2; nt++)
                    bvn[nt] = g_Wfh[((nbase + nt) * 16 + ktn) * 32 + lane];

                const int kb = kt * 16 + 2 * qid;
                uint32_t a[4][4];
#pragma unroll
                for (int mt = 0; mt < 4; mt++) {
                    const __nv_bfloat16* hb = hcur + (mt * 16 + gid) * HSTRH;
                    a[mt][0] = *(const uint32_t*)(hb + kb);
                    a[mt][1] = *(const uint32_t*)(hb + 8 * HSTRH + kb);
                    a[mt][2] = *(const uint32_t*)(hb + kb + 8);
                    a[mt][3] = *(const uint32_t*)(hb + 8 * HSTRH + kb + 8);
                }
#pragma unroll
                for (int nt = 0; nt < 2; nt++)
#pragma unroll
                    for (int mt = 0; mt < 4; mt++)
                        mma_bf16(cacc[nt][mt], a[mt], (const uint32_t*)&bv[nt]);
#pragma unroll
                for (int nt = 0; nt < 2; nt++) bv[nt] = bvn[nt];
            }

            // pointwise LSTM for this quarter's 2 ntiles x 4 m-tiles
#pragma unroll
            for (int nt = 0; nt < 2; nt++) {
                const int ni = q4 * 2 + nt;
                const int j  = (w * 8 + ni) * 2 + (qid >> 1);
#pragma unroll
                for (int mt = 0; mt < 4; mt++) {
                    float* C = cacc[nt][mt];
                    float sx = (qid & 1) ? C[0] : C[2];
                    float sy = (qid & 1) ? C[1] : C[3];
                    float rx = __shfl_xor_sync(0xffffffffu, sx, 1);
                    float ry = __shfl_xor_sync(0xffffffffu, sy, 1);
                    float gi, gf, gg, go;
                    if (qid & 1) { gi = rx;   gf = ry;   gg = C[2]; go = C[3]; }
                    else         { gi = C[0]; gf = C[1]; gg = rx;   go = ry;  }

                    float hh = 0.f;
                    if (act[mt]) {
                        uint2 raw = *(const uint2*)(xr[mt] + 4 * j);
                        float2 x01 = __half22float2(*(const __half2*)&raw.x);
                        float2 x23 = __half22float2(*(const __half2*)&raw.y);
                        float vi = x01.x + keep[mt] * gi;
                        float vf = x01.y + keep[mt] * gf;
                        float vg = x23.x + keep[mt] * gg;
                        float vo = x23.y + keep[mt] * go;
                        float cc = sigf(vf) * (cell[ni][mt] * keep[mt]) + sigf(vi) * tanhf(vg);
                        hh = sigf(vo) * tanhf(cc);
                        cell[ni][mt] = cc;
                        prj[mt] += wp8[ni] * hh;
                    }
                    hnxt[(mt * 16 + sb0) * HSTRH + j] = __float2bfloat16(hh);
                }
            }
        }

        // projection partials (qid ^ 2 shares the same stream)
#pragma unroll
        for (int mt = 0; mt < 4; mt++)
            prj[mt] += __shfl_xor_sync(0xffffffffu, prj[mt], 2);
        if (qid < 2) {
#pragma unroll
            for (int mt = 0; mt < 4; mt++)
                red[(size_t)rb * SPB_ * 16 + (mt * 16 + sb0) * 16 + w] = prj[mt];
        }
        __syncthreads();

        if (tid < SPB_) {
            int t = s_start[tid] + r;
            if (t < s_end[tid]) {
                float sum = bpv;
#pragma unroll
                for (int i = 0; i < 16; i++)
                    sum += red[(size_t)rb * SPB_ * 16 + tid * 16 + i];
                out[t * B_ + s_b[tid]] = sum;
            }
        }
        // no trailing sync: red double-buffered by rb, h by rb^1
    }
}

// ---------------- launch ----------------------------------------------------
extern "C" void kernel_launch(void* const* d_in, const int* in_sizes, int n_in,
                              void* d_out, int out_size) {
    const float* x     = (const float*)d_in[0];
    const int*   reset = (const int*)  d_in[1];
    const float* Wih   = (const float*)d_in[2];
    const float* Whh   = (const float*)d_in[3];
    const float* bih   = (const float*)d_in[4];
    const float* bhh   = (const float*)d_in[5];
    const float* Wp    = (const float*)d_in[6];
    const float* bp    = (const float*)d_in[7];
    float* out = (float*)d_out;

    const int rsm = 2 * HBUFH * 2 + 2 * SPB_ * 16 * 4 + 3 * SPB_ * 4 + 128;
    static int attr_set = 0;
    if (!attr_set) {
        cudaFuncSetAttribute(k_gemm_tf32,
                             cudaFuncAttributeMaxDynamicSharedMemorySize, 65536);
        cudaFuncSetAttribute(k_recur,
                             cudaFuncAttributeMaxDynamicSharedMemorySize, rsm);
        attr_set = 1;
    }

    k_bounds<<<B_, 320>>>(reset);
    k_prep<<<2048, 256>>>(Wih, Whh, bih, bhh);

    dim3 grid(G4_ / GBN, (T_ * B_) / GBM);
    k_gemm_tf32<<<grid, 256, 65536>>>(x);

    k_recur<<<NBLK_, 512, rsm>>>(reset, Wp, bp, out);
}

// round 14
// speedup vs baseline: 1.6309x; 1.1284x over previous
#include <cuda_runtime.h>
#include <cuda_bf16.h>
#include <cuda_fp16.h>
#include <cstdint>
#include <cstdio>

#define T_  4096
#define B_  32
#define D_  512
#define H_  256
#define G4_ 1024            // 4*H
#define P_  296             // time-chunks per batch row
#define SPB_ 64             // streams per block
#define NBLK_ ((B_ * P_) / SPB_)   // 148 blocks

// ---------------- scratch (static device globals; no allocations) ----------
__device__ __half g_xwh[(size_t)B_ * T_ * G4_]; // [b][t][col'] fp16, col'=4*j+q (256 MB)
__device__ float g_Wp[G4_ * D_];                // W_ih rows permuted to col' order (2 MB)
__device__ uint2 g_Wfh[128 * 16 * 32];          // bf16 fragment-packed W_hh (512 KB)
__device__ float g_bb[G4_];                     // b_ih + b_hh (original order)
__device__ int   g_bound[B_][P_ + 1];           // chunk boundaries per batch row

// ---------------- stage 0: chunk boundaries at reset points ----------------
__global__ void k_bounds(const int* __restrict__ reset) {
    int b = blockIdx.x;
    int k = threadIdx.x;
    if (k == 0) {
        g_bound[b][0] = 0;
    } else if (k < P_) {
        int t = (k * T_) / P_;
        while (t < T_ && reset[t * B_ + b] == 0) t++;
        g_bound[b][k] = t;          // either a reset point (state=0) or T
    } else if (k == P_) {
        g_bound[b][P_] = T_;
    }
}

// ---------------- stage 0b: permute W_ih, pack bf16 W_hh frags, biases -----
// permuted col cp <-> original gate row g = (cp&3)*256 + (cp>>2)
__global__ void k_prep(const float* __restrict__ Wih,
                       const float* __restrict__ Whh,
                       const float* __restrict__ bih,
                       const float* __restrict__ bhh) {
    int idx = blockIdx.x * blockDim.x + threadIdx.x;   // grid covers 524288
    if (idx < G4_ * D_) {                              // g_Wp: permuted W_ih copy
        int cp = idx >> 9;
        int d  = idx & 511;
        int g  = ((cp & 3) << 8) + (cp >> 2);
        g_Wp[idx] = Wih[g * D_ + d];
    }
    if (idx < 128 * 16 * 32) {                         // g_Wfh: bf16 B-fragments
        int lane  = idx & 31;
        int kt    = (idx >> 5) & 15;
        int ntile = idx >> 9;
        int gid = lane >> 2, qid = lane & 3;
        int colp = ntile * 8 + gid;
        int g = ((colp & 3) << 8) + (colp >> 2);
        int k0 = kt * 16 + 2 * qid;
        const float* wr = Whh + (size_t)g * H_;
        __nv_bfloat162 lo = { __float2bfloat16(wr[k0]),     __float2bfloat16(wr[k0 + 1]) };
        __nv_bfloat162 hi = { __float2bfloat16(wr[k0 + 8]), __float2bfloat16(wr[k0 + 9]) };
        uint2 v;
        v.x = *(const uint32_t*)&lo;
        v.y = *(const uint32_t*)&hi;
        g_Wfh[idx] = v;
    }
    if (idx < G4_) g_bb[idx] = bih[idx] + bhh[idx];
}

// ---------------- stage 1: xW GEMM via fp16 mma.m16n8k16 -------------------
// fp16 mantissa == tf32 mantissa (10 bits): no precision change vs tf32,
// but half the mma instructions and half the smem traffic.
#define GBM 128
#define GBN 128
#define GBK 32
#define ASTR 18                 // uint32 per smem row: 16 data (32 halves) + 2 pad
#define ABUF (GBM * ASTR)       // uint32 per tile buffer (2304)
#define BBOFF (2 * ABUF)        // B tiles start (uint32 index)

__device__ __forceinline__ void mma_f16(float* c, const uint32_t* a, const uint32_t* b) {
    asm volatile(
        "mma.sync.aligned.m16n8k16.row.col.f32.f16.f16.f32 "
        "{%0,%1,%2,%3},{%4,%5,%6,%7},{%8,%9},{%0,%1,%2,%3};"
        : "+f"(c[0]), "+f"(c[1]), "+f"(c[2]), "+f"(c[3])
        : "r"(a[0]), "r"(a[1]), "r"(a[2]), "r"(a[3]), "r"(b[0]), "r"(b[1]));
}

__global__ __launch_bounds__(256) void k_gemm_f16(const float* __restrict__ A) {
    __shared__ uint32_t smu[4 * ABUF];   // A[2] then B[2], 36864 B
    __shared__ float bias_sm[GBN];

    const int tid  = threadIdx.x;
    const int warp = tid >> 5;
    const int lane = tid & 31;
    const int wm   = warp >> 1;          // 0..3
    const int wn   = warp & 1;           // 0..1
    const int gid  = lane >> 2;          // groupID 0..7
    const int qid  = lane & 3;           // thread-in-group 0..3
    const int m0   = blockIdx.y * GBM;
    const int n0   = blockIdx.x * GBN;   // permuted col base

    const int crow = tid >> 1;
    const int cc4  = (tid & 1) * 4;
    const float* gA = A    + (size_t)(m0 + crow) * D_ + cc4 * 4;
    const float* gB = g_Wp + (size_t)(n0 + crow) * D_ + cc4 * 4;

    if (tid < GBN) {
        int cp = n0 + tid;
        bias_sm[tid] = g_bb[((cp & 3) << 8) + (cp >> 2)];
    }

    float acc[2][8][4];
#pragma unroll
    for (int i = 0; i < 2; i++)
#pragma unroll
        for (int j = 0; j < 8; j++)
#pragma unroll
            for (int q = 0; q < 4; q++) acc[i][j][q] = 0.f;

    float4 ra[4], rb[4];

#define LOADG(k0)                                                   \
    {                                                               \
        _Pragma("unroll")                                           \
        for (int i = 0; i < 4; i++) {                               \
            ra[i] = *(const float4*)(gA + (k0) + i * 4);            \
            rb[i] = *(const float4*)(gB + (k0) + i * 4);            \
        }                                                           \
    }

#define STORES(buf)                                                             \
    {                                                                           \
        _Pragma("unroll")                                                       \
        for (int i = 0; i < 4; i++) {                                           \
            __half2 a0 = __floats2half2_rn(ra[i].x, ra[i].y);                   \
            __half2 a1 = __floats2half2_rn(ra[i].z, ra[i].w);                   \
            uint2 va = { *(uint32_t*)&a0, *(uint32_t*)&a1 };                    \
            *(uint2*)&smu[(buf) * ABUF + crow * ASTR + (cc4 + i) * 2] = va;     \
            __half2 b0 = __floats2half2_rn(rb[i].x, rb[i].y);                   \
            __half2 b1 = __floats2half2_rn(rb[i].z, rb[i].w);                   \
            uint2 vb = { *(uint32_t*)&b0, *(uint32_t*)&b1 };                    \
            *(uint2*)&smu[BBOFF + (buf) * ABUF + crow * ASTR + (cc4 + i) * 2] = vb; \
        }                                                                       \
    }

    LOADG(0)
    STORES(0)
    __syncthreads();

    const int NKT = D_ / GBK;   // 16
    for (int kt = 0; kt < NKT; kt++) {
        const int cur = kt & 1;
        if (kt + 1 < NKT) LOADG((kt + 1) * GBK)

#pragma unroll
        for (int ks = 0; ks < 2; ks++) {     // two k16 steps per 32-chunk
            uint32_t af[2][4], bf[8][2];
#pragma unroll
            for (int ma = 0; ma < 2; ma++) {
                int rw = wm * 32 + ma * 16 + gid;
                int b0 = cur * ABUF + rw * ASTR + ks * 8 + qid;
                int b8 = b0 + 8 * ASTR;
                af[ma][0] = smu[b0];
                af[ma][1] = smu[b8];
                af[ma][2] = smu[b0 + 4];
                af[ma][3] = smu[b8 + 4];
            }
#pragma unroll
            for (int na = 0; na < 8; na++) {
                int rn = wn * 64 + na * 8 + gid;
                int bb = BBOFF + cur * ABUF + rn * ASTR + ks * 8 + qid;
                bf[na][0] = smu[bb];
                bf[na][1] = smu[bb + 4];
            }
#pragma unroll
            for (int na = 0; na < 8; na++)
#pragma unroll
                for (int ma = 0; ma < 2; ma++)
                    mma_f16(acc[ma][na], af[ma], bf[na]);
        }

        if (kt + 1 < NKT) STORES(cur ^ 1)
        __syncthreads();
    }

    // epilogue: +bias, contiguous half2 stores into permuted fp16 layout
#pragma unroll
    for (int na = 0; na < 8; na++) {
        const int cl = wn * 64 + na * 8 + qid * 2;
        const float bi0 = bias_sm[cl];
        const float bi1 = bias_sm[cl + 1];
#pragma unroll
        for (int ma = 0; ma < 2; ma++) {
            int m1 = m0 + wm * 32 + ma * 16 + gid;
            int m2 = m1 + 8;
            {
                int t = m1 >> 5, b = m1 & 31;
                __half2 v = __floats2half2_rn(acc[ma][na][0] + bi0, acc[ma][na][1] + bi1);
                *(__half2*)(g_xwh + ((size_t)b * T_ + t) * G4_ + n0 + cl) = v;
            }
            {
                int t = m2 >> 5, b = m2 & 31;
                __half2 v = __floats2half2_rn(acc[ma][na][2] + bi0, acc[ma][na][3] + bi1);
                *(__half2*)(g_xwh + ((size_t)b * T_ + t) * G4_ + n0 + cl) = v;
            }
        }
    }
#undef LOADG
#undef STORES
}

// ---------------- stage 2: bf16 recurrence, 64 streams per block -----------
__device__ __forceinline__ float sigf(float x) {
    return 1.f / (1.f + __expf(-x));
}

__device__ __forceinline__ void mma_bf16(float* c, const uint32_t* a, const uint32_t* b) {
    asm volatile(
        "mma.sync.aligned.m16n8k16.row.col.f32.bf16.bf16.f32 "
        "{%0,%1,%2,%3},{%4,%5,%6,%7},{%8,%9},{%0,%1,%2,%3};"
        : "+f"(c[0]), "+f"(c[1]), "+f"(c[2]), "+f"(c[3])
        : "r"(a[0]), "r"(a[1]), "r"(a[2]), "r"(a[3]), "r"(b[0]), "r"(b[1]));
}

#define HSTRH 264              // h row stride in halves: 256 + pad 8
#define HBUFH (SPB_ * HSTRH)   // halves per h buffer

__global__ __launch_bounds__(512, 1) void k_recur(const int* __restrict__ reset,
                                                  const float* __restrict__ Wp,
                                                  const float* __restrict__ bp,
                                                  float* __restrict__ out) {
    extern __shared__ char smr[];
    __nv_bfloat16* hsb = (__nv_bfloat16*)smr;              // [2][64][264] bf16
    float* red = (float*)(smr + 2 * HBUFH * 2);            // [2][64][16]
    int*   meta = (int*)(red + 2 * SPB_ * 16);
    int* s_start = meta;
    int* s_end   = meta + SPB_;
    int* s_b     = meta + 2 * SPB_;

    const int tid  = threadIdx.x;
    const int w    = tid >> 5;              // warp 0..15 -> ntiles w*8..w*8+7
    const int lane = tid & 31;
    const int gid  = lane >> 2;
    const int qid  = lane & 3;

    if (tid < SPB_) {
        int sid = blockIdx.x * SPB_ + tid;
        int b = sid / P_;
        int k = sid % P_;
        s_start[tid] = g_bound[b][k];
        s_end[tid]   = g_bound[b][k + 1];
        s_b[tid]     = b;
    }
    {
        uint32_t* hz = (uint32_t*)hsb;
        for (int q = tid; q < HBUFH / 2; q += 512) hz[q] = 0u;   // zero buffer 0
    }
    __syncthreads();

    const int sb0 = gid + 8 * (qid & 1);    // stream base within 16

    int maxlen = 0;
    for (int s = 0; s < SPB_; s++) maxlen = max(maxlen, s_end[s] - s_start[s]);

    float wp8[8];
#pragma unroll
    for (int i = 0; i < 8; i++) wp8[i] = Wp[(w * 8 + i) * 2 + (qid >> 1)];
    const float bpv = bp[0];

    float cell[8][4];
#pragma unroll
    for (int i = 0; i < 8; i++)
#pragma unroll
        for (int m = 0; m < 4; m++) cell[i][m] = 0.f;

    for (int r = 0; r < maxlen; r++) {
        const int rb = r & 1;
        const __nv_bfloat16* hcur = hsb + rb * HBUFH;
        __nv_bfloat16*       hnxt = hsb + (rb ^ 1) * HBUFH;

        // per-step state for this thread's 4 streams
        bool  act[4];
        float keep[4];
        const __half* xr[4];
#pragma unroll
        for (int mt = 0; mt < 4; mt++) {
            const int s = mt * 16 + sb0;
            const int t = s_start[s] + r;
            act[mt] = t < s_end[s];
            if (act[mt]) {
                const int b = s_b[s];
                keep[mt] = (reset[t * B_ + b] != 0) ? 0.f : 1.f;
                xr[mt] = g_xwh + ((size_t)b * T_ + t) * G4_;
            } else {
                keep[mt] = 0.f;
                xr[mt] = g_xwh;
            }
        }
        float prj[4] = {0.f, 0.f, 0.f, 0.f};

#pragma unroll
        for (int q4 = 0; q4 < 4; q4++) {
            float cacc[2][4][4];
#pragma unroll
            for (int nt = 0; nt < 2; nt++)
#pragma unroll
                for (int mt = 0; mt < 4; mt++)
#pragma unroll
                    for (int q = 0; q < 4; q++) cacc[nt][mt][q] = 0.f;

            const int nbase = w * 8 + q4 * 2;
            // depth-2 weight prefetch pipeline (L2 latency ~250cyc >> 1 iter)
            uint2 bva[2], bvb[2], bvc[2];
#pragma unroll
            for (int nt = 0; nt < 2; nt++) {
                bva[nt] = g_Wfh[((nbase + nt) * 16 + 0) * 32 + lane];
                bvb[nt] = g_Wfh[((nbase + nt) * 16 + 1) * 32 + lane];
            }

            for (int kt = 0; kt < 16; kt++) {
                const int ktn = (kt + 2) & 15;
#pragma unroll
                for (int nt = 0; nt < 2; nt++)
                    bvc[nt] = g_Wfh[((nbase + nt) * 16 + ktn) * 32 + lane];

                const int kb = kt * 16 + 2 * qid;
                uint32_t a[4][4];
#pragma unroll
                for (int mt = 0; mt < 4; mt++) {
                    const __nv_bfloat16* hb = hcur + (mt * 16 + gid) * HSTRH;
                    a[mt][0] = *(const uint32_t*)(hb + kb);
                    a[mt][1] = *(const uint32_t*)(hb + 8 * HSTRH + kb);
                    a[mt][2] = *(const uint32_t*)(hb + kb + 8);
                    a[mt][3] = *(const uint32_t*)(hb + 8 * HSTRH + kb + 8);
                }
#pragma unroll
                for (int nt = 0; nt < 2; nt++)
#pragma unroll
                    for (int mt = 0; mt < 4; mt++)
                        mma_bf16(cacc[nt][mt], a[mt], (const uint32_t*)&bva[nt]);
#pragma unroll
                for (int nt = 0; nt < 2; nt++) {
                    bva[nt] = bvb[nt];
                    bvb[nt] = bvc[nt];
                }
            }

            // pointwise LSTM for this quarter's 2 ntiles x 4 m-tiles
#pragma unroll
            for (int nt = 0; nt < 2; nt++) {
                const int ni = q4 * 2 + nt;
                const int j  = (w * 8 + ni) * 2 + (qid >> 1);
#pragma unroll
                for (int mt = 0; mt < 4; mt++) {
                    float* C = cacc[nt][mt];
                    float sx = (qid & 1) ? C[0] : C[2];
                    float sy = (qid & 1) ? C[1] : C[3];
                    float rx = __shfl_xor_sync(0xffffffffu, sx, 1);
                    float ry = __shfl_xor_sync(0xffffffffu, sy, 1);
                    float gi, gf, gg, go;
                    if (qid & 1) { gi = rx;   gf = ry;   gg = C[2]; go = C[3]; }
                    else         { gi = C[0]; gf = C[1]; gg = rx;   go = ry;  }

                    float hh = 0.f;
                    if (act[mt]) {
                        uint2 raw = *(const uint2*)(xr[mt] + 4 * j);
                        float2 x01 = __half22float2(*(const __half2*)&raw.x);
                        float2 x23 = __half22float2(*(const __half2*)&raw.y);
                        float vi = x01.x + keep[mt] * gi;
                        float vf = x01.y + keep[mt] * gf;
                        float vg = x23.x + keep[mt] * gg;
                        float vo = x23.y + keep[mt] * go;
                        float cc = sigf(vf) * (cell[ni][mt] * keep[mt]) + sigf(vi) * tanhf(vg);
                        hh = sigf(vo) * tanhf(cc);
                        cell[ni][mt] = cc;
                        prj[mt] += wp8[ni] * hh;
                    }
                    hnxt[(mt * 16 + sb0) * HSTRH + j] = __float2bfloat16(hh);
                }
            }
        }

        // projection partials (qid ^ 2 shares the same stream)
#pragma unroll
        for (int mt = 0; mt < 4; mt++)
            prj[mt] += __shfl_xor_sync(0xffffffffu, prj[mt], 2);
        if (qid < 2) {
#pragma unroll
            for (int mt = 0; mt < 4; mt++)
                red[(size_t)rb * SPB_ * 16 + (mt * 16 + sb0) * 16 + w] = prj[mt];
        }
        __syncthreads();

        if (tid < SPB_) {
            int t = s_start[tid] + r;
            if (t < s_end[tid]) {
                float sum = bpv;
#pragma unroll
                for (int i = 0; i < 16; i++)
                    sum += red[(size_t)rb * SPB_ * 16 + tid * 16 + i];
                out[t * B_ + s_b[tid]] = sum;
            }
        }
        // no trailing sync: red double-buffered by rb, h by rb^1
    }
}

// ---------------- launch ----------------------------------------------------
extern "C" void kernel_launch(void* const* d_in, const int* in_sizes, int n_in,
                              void* d_out, int out_size) {
    const float* x     = (const float*)d_in[0];
    const int*   reset = (const int*)  d_in[1];
    const float* Wih   = (const float*)d_in[2];
    const float* Whh   = (const float*)d_in[3];
    const float* bih   = (const float*)d_in[4];
    const float* bhh   = (const float*)d_in[5];
    const float* Wp    = (const float*)d_in[6];
    const float* bp    = (const float*)d_in[7];
    float* out = (float*)d_out;

    const int rsm = 2 * HBUFH * 2 + 2 * SPB_ * 16 * 4 + 3 * SPB_ * 4 + 128;
    static int attr_set = 0;
    if (!attr_set) {
        cudaFuncSetAttribute(k_recur,
                             cudaFuncAttributeMaxDynamicSharedMemorySize, rsm);
        attr_set = 1;
    }

    k_bounds<<<B_, 320>>>(reset);
    k_prep<<<2048, 256>>>(Wih, Whh, bih, bhh);

    dim3 grid(G4_ / GBN, (T_ * B_) / GBM);
    k_gemm_f16<<<grid, 256>>>(x);

    k_recur<<<NBLK_, 512, rsm>>>(reset, Wp, bp, out);
}

// round 16
// speedup vs baseline: 2.0232x; 1.2405x over previous
#include <cuda_runtime.h>
#include <cuda_bf16.h>
#include <cuda_fp16.h>
#include <cstdint>
#include <cstdio>

#define T_  4096
#define B_  32
#define D_  512
#define H_  256
#define G4_ 1024            // 4*H
#define P_  296             // time-chunks per batch row
#define SPB_ 64             // streams per block
#define NBLK_ ((B_ * P_) / SPB_)   // 148 blocks

// ---------------- scratch (static device globals; no allocations) ----------
__device__ __half g_xwh[(size_t)B_ * T_ * G4_]; // [b][t][col'] fp16, col'=4*j+q (256 MB)
__device__ float g_Wp[G4_ * D_];                // W_ih rows permuted to col' order (2 MB)
__device__ uint2 g_Wfh[128 * 16 * 32];          // bf16 fragment-packed W_hh (512 KB)
__device__ float g_bb[G4_];                     // b_ih + b_hh (original order)
__device__ int   g_bound[B_][P_ + 1];           // chunk boundaries per batch row

// ---------------- stage 0: chunk boundaries at reset points ----------------
__global__ void k_bounds(const int* __restrict__ reset) {
    int b = blockIdx.x;
    int k = threadIdx.x;
    if (k == 0) {
        g_bound[b][0] = 0;
    } else if (k < P_) {
        int t = (k * T_) / P_;
        while (t < T_ && reset[t * B_ + b] == 0) t++;
        g_bound[b][k] = t;          // either a reset point (state=0) or T
    } else if (k == P_) {
        g_bound[b][P_] = T_;
    }
}

// ---------------- stage 0b: permute W_ih, pack bf16 W_hh frags, biases -----
// permuted col cp <-> original gate row g = (cp&3)*256 + (cp>>2)
__global__ void k_prep(const float* __restrict__ Wih,
                       const float* __restrict__ Whh,
                       const float* __restrict__ bih,
                       const float* __restrict__ bhh) {
    int idx = blockIdx.x * blockDim.x + threadIdx.x;   // grid covers 524288
    if (idx < G4_ * D_) {                              // g_Wp: permuted W_ih copy
        int cp = idx >> 9;
        int d  = idx & 511;
        int g  = ((cp & 3) << 8) + (cp >> 2);
        g_Wp[idx] = Wih[g * D_ + d];
    }
    if (idx < 128 * 16 * 32) {                         // g_Wfh: bf16 B-fragments
        int lane  = idx & 31;
        int kt    = (idx >> 5) & 15;
        int ntile = idx >> 9;
        int gid = lane >> 2, qid = lane & 3;
        int colp = ntile * 8 + gid;
        int g = ((colp & 3) << 8) + (colp >> 2);
        int k0 = kt * 16 + 2 * qid;
        const float* wr = Whh + (size_t)g * H_;
        __nv_bfloat162 lo = { __float2bfloat16(wr[k0]),     __float2bfloat16(wr[k0 + 1]) };
        __nv_bfloat162 hi = { __float2bfloat16(wr[k0 + 8]), __float2bfloat16(wr[k0 + 9]) };
        uint2 v;
        v.x = *(const uint32_t*)&lo;
        v.y = *(const uint32_t*)&hi;
        g_Wfh[idx] = v;
    }
    if (idx < G4_) g_bb[idx] = bih[idx] + bhh[idx];
}

// ---------------- stage 1: xW GEMM via fp16 mma.m16n8k16 + ldmatrix --------
#define GBM 128
#define GBN 128
#define GBK 32
#define ASTR 20                 // uint32 per smem row: 16 data + 4 pad (80B, 16B-aligned)
#define ABUF (GBM * ASTR)       // uint32 per tile buffer (2560)
#define BBOFF (2 * ABUF)        // B tiles start (uint32 index)

__device__ __forceinline__ void mma_f16(float* c, const uint32_t* a, const uint32_t* b) {
    asm volatile(
        "mma.sync.aligned.m16n8k16.row.col.f32.f16.f16.f32 "
        "{%0,%1,%2,%3},{%4,%5,%6,%7},{%8,%9},{%0,%1,%2,%3};"
        : "+f"(c[0]), "+f"(c[1]), "+f"(c[2]), "+f"(c[3])
        : "r"(a[0]), "r"(a[1]), "r"(a[2]), "r"(a[3]), "r"(b[0]), "r"(b[1]));
}

#define LDM4(r0, r1, r2, r3, adr)                                             \
    asm volatile("ldmatrix.sync.aligned.m8n8.x4.shared.b16 {%0,%1,%2,%3}, [%4];" \
                 : "=r"(r0), "=r"(r1), "=r"(r2), "=r"(r3) : "r"(adr))

__global__ __launch_bounds__(256) void k_gemm_f16(const float* __restrict__ A) {
    __shared__ uint32_t smu[4 * ABUF];   // A[2] then B[2], 40960 B
    __shared__ float bias_sm[GBN];

    const int tid  = threadIdx.x;
    const int warp = tid >> 5;
    const int lane = tid & 31;
    const int wm   = warp >> 1;          // 0..3
    const int wn   = warp & 1;           // 0..1
    const int qid  = lane & 3;           // thread-in-group 0..3
    const int m0   = blockIdx.y * GBM;
    const int n0   = blockIdx.x * GBN;   // permuted col base

    const int crow = tid >> 1;
    const int cc4  = (tid & 1) * 4;
    const float* gA = A    + (size_t)(m0 + crow) * D_ + cc4 * 4;
    const float* gB = g_Wp + (size_t)(n0 + crow) * D_ + cc4 * 4;

    if (tid < GBN) {
        int cp = n0 + tid;
        bias_sm[tid] = g_bb[((cp & 3) << 8) + (cp >> 2)];
    }

    // ldmatrix per-lane address terms (uint32 units)
    const uint32_t smbase = (uint32_t)__cvta_generic_to_shared(smu);
    const int mi = lane >> 3;            // matrix index 0..3
    const int ri = lane & 7;             // row within matrix
    int aterm[2], bterm[4];
#pragma unroll
    for (int ma = 0; ma < 2; ma++)
        aterm[ma] = (wm * 32 + ma * 16 + (mi & 1) * 8 + ri) * ASTR + (mi >> 1) * 4;
#pragma unroll
    for (int p = 0; p < 4; p++)
        bterm[p] = BBOFF + (wn * 64 + (2 * p + (mi >> 1)) * 8 + ri) * ASTR + (mi & 1) * 4;

    float acc[2][8][4];
#pragma unroll
    for (int i = 0; i < 2; i++)
#pragma unroll
        for (int j = 0; j < 8; j++)
#pragma unroll
            for (int q = 0; q < 4; q++) acc[i][j][q] = 0.f;

    float4 ra[4], rb[4];

#define LOADG(k0)                                                   \
    {                                                               \
        _Pragma("unroll")                                           \
        for (int i = 0; i < 4; i++) {                               \
            ra[i] = *(const float4*)(gA + (k0) + i * 4);            \
            rb[i] = *(const float4*)(gB + (k0) + i * 4);            \
        }                                                           \
    }

#define STORES(buf)                                                             \
    {                                                                           \
        _Pragma("unroll")                                                       \
        for (int i = 0; i < 4; i++) {                                           \
            __half2 a0 = __floats2half2_rn(ra[i].x, ra[i].y);                   \
            __half2 a1 = __floats2half2_rn(ra[i].z, ra[i].w);                   \
            uint2 va = { *(uint32_t*)&a0, *(uint32_t*)&a1 };                    \
            *(uint2*)&smu[(buf) * ABUF + crow * ASTR + (cc4 + i) * 2] = va;     \
            __half2 b0 = __floats2half2_rn(rb[i].x, rb[i].y);                   \
            __half2 b1 = __floats2half2_rn(rb[i].z, rb[i].w);                   \
            uint2 vb = { *(uint32_t*)&b0, *(uint32_t*)&b1 };                    \
            *(uint2*)&smu[BBOFF + (buf) * ABUF + crow * ASTR + (cc4 + i) * 2] = vb; \
        }                                                                       \
    }

    LOADG(0)
    STORES(0)
    __syncthreads();

    const int NKT = D_ / GBK;   // 16
    for (int kt = 0; kt < NKT; kt++) {
        const int cur = kt & 1;
        if (kt + 1 < NKT) LOADG((kt + 1) * GBK)

#pragma unroll
        for (int ks = 0; ks < 2; ks++) {     // two k16 steps per 32-chunk
            const uint32_t kadd = smbase + (cur * ABUF + ks * 8) * 4;
            uint32_t af[2][4], bf[8][2];
#pragma unroll
            for (int ma = 0; ma < 2; ma++)
                LDM4(af[ma][0], af[ma][1], af[ma][2], af[ma][3], kadd + aterm[ma] * 4);
#pragma unroll
            for (int p = 0; p < 4; p++)
                LDM4(bf[2 * p][0], bf[2 * p][1], bf[2 * p + 1][0], bf[2 * p + 1][1],
                     kadd + bterm[p] * 4);
#pragma unroll
            for (int na = 0; na < 8; na++)
#pragma unroll
                for (int ma = 0; ma < 2; ma++)
                    mma_f16(acc[ma][na], af[ma], bf[na]);
        }

        if (kt + 1 < NKT) STORES(cur ^ 1)
        __syncthreads();
    }

    // epilogue: +bias, contiguous half2 stores into permuted fp16 layout
    const int gid = lane >> 2;
#pragma unroll
    for (int na = 0; na < 8; na++) {
        const int cl = wn * 64 + na * 8 + qid * 2;
        const float bi0 = bias_sm[cl];
        const float bi1 = bias_sm[cl + 1];
#pragma unroll
        for (int ma = 0; ma < 2; ma++) {
            int m1 = m0 + wm * 32 + ma * 16 + gid;
            int m2 = m1 + 8;
            {
                int t = m1 >> 5, b = m1 & 31;
                __half2 v = __floats2half2_rn(acc[ma][na][0] + bi0, acc[ma][na][1] + bi1);
                *(__half2*)(g_xwh + ((size_t)b * T_ + t) * G4_ + n0 + cl) = v;
            }
            {
                int t = m2 >> 5, b = m2 & 31;
                __half2 v = __floats2half2_rn(acc[ma][na][2] + bi0, acc[ma][na][3] + bi1);
                *(__half2*)(g_xwh + ((size_t)b * T_ + t) * G4_ + n0 + cl) = v;
            }
        }
    }
#undef LOADG
#undef STORES
}

// ---------------- stage 2: bf16 recurrence, 64 streams per block -----------
__device__ __forceinline__ float tanha(float x) {
    float r;
    asm("tanh.approx.f32 %0, %1;" : "=f"(r) : "f"(x));
    return r;
}
__device__ __forceinline__ float sigf(float x) {
    return fmaf(tanha(x * 0.5f), 0.5f, 0.5f);
}

__device__ __forceinline__ void mma_bf16(float* c, const uint32_t* a, const uint32_t* b) {
    asm volatile(
        "mma.sync.aligned.m16n8k16.row.col.f32.bf16.bf16.f32 "
        "{%0,%1,%2,%3},{%4,%5,%6,%7},{%8,%9},{%0,%1,%2,%3};"
        : "+f"(c[0]), "+f"(c[1]), "+f"(c[2]), "+f"(c[3])
        : "r"(a[0]), "r"(a[1]), "r"(a[2]), "r"(a[3]), "r"(b[0]), "r"(b[1]));
}

#define HSTRH 264              // h row stride in halves: 256 + pad 8
#define HBUFH (SPB_ * HSTRH)   // halves per h buffer

__global__ __launch_bounds__(512, 1) void k_recur(const int* __restrict__ reset,
                                                  const float* __restrict__ Wp,
                                                  const float* __restrict__ bp,
                                                  float* __restrict__ out) {
    extern __shared__ char smr[];
    __nv_bfloat16* hsb = (__nv_bfloat16*)smr;              // [2][64][264] bf16
    float* red = (float*)(smr + 2 * HBUFH * 2);            // [2][64][16]
    int*   meta = (int*)(red + 2 * SPB_ * 16);
    int* s_start = meta;
    int* s_end   = meta + SPB_;
    int* s_b     = meta + 2 * SPB_;

    const int tid  = threadIdx.x;
    const int w    = tid >> 5;              // warp 0..15 -> ntiles w*8..w*8+7
    const int lane = tid & 31;
    const int gid  = lane >> 2;
    const int qid  = lane & 3;

    if (tid < SPB_) {
        int sid = blockIdx.x * SPB_ + tid;
        int b = sid / P_;
        int k = sid % P_;
        s_start[tid] = g_bound[b][k];
        s_end[tid]   = g_bound[b][k + 1];
        s_b[tid]     = b;
    }
    {
        uint32_t* hz = (uint32_t*)hsb;
        for (int q = tid; q < HBUFH / 2; q += 512) hz[q] = 0u;   // zero buffer 0
    }
    __syncthreads();

    const int sb0 = gid + 8 * (qid & 1);    // stream base within 16

    int maxlen = 0;
    for (int s = 0; s < SPB_; s++) maxlen = max(maxlen, s_end[s] - s_start[s]);

    float wp8[8];
#pragma unroll
    for (int i = 0; i < 8; i++) wp8[i] = Wp[(w * 8 + i) * 2 + (qid >> 1)];
    const float bpv = bp[0];

    float cell[8][4];
#pragma unroll
    for (int i = 0; i < 8; i++)
#pragma unroll
        for (int m = 0; m < 4; m++) cell[i][m] = 0.f;

    for (int r = 0; r < maxlen; r++) {
        const int rb = r & 1;
        const __nv_bfloat16* hcur = hsb + rb * HBUFH;
        __nv_bfloat16*       hnxt = hsb + (rb ^ 1) * HBUFH;

        // per-step state for this thread's 4 streams
        bool  act[4];
        float keep[4];
        const __half* xr[4];
#pragma unroll
        for (int mt = 0; mt < 4; mt++) {
            const int s = mt * 16 + sb0;
            const int t = s_start[s] + r;
            act[mt] = t < s_end[s];
            if (act[mt]) {
                const int b = s_b[s];
                keep[mt] = (reset[t * B_ + b] != 0) ? 0.f : 1.f;
                xr[mt] = g_xwh + ((size_t)b * T_ + t) * G4_;
            } else {
                keep[mt] = 0.f;
                xr[mt] = g_xwh;
            }
        }
        float prj[4] = {0.f, 0.f, 0.f, 0.f};

#pragma unroll
        for (int q4 = 0; q4 < 4; q4++) {
            float cacc[2][4][4];
#pragma unroll
            for (int nt = 0; nt < 2; nt++)
#pragma unroll
                for (int mt = 0; mt < 4; mt++)
#pragma unroll
                    for (int q = 0; q < 4; q++) cacc[nt][mt][q] = 0.f;

            const int nbase = w * 8 + q4 * 2;
            uint2 bv[2], bvn[2];
#pragma unroll
            for (int nt = 0; nt < 2; nt++)
                bv[nt] = g_Wfh[((nbase + nt) * 16) * 32 + lane];

            for (int kt = 0; kt < 16; kt++) {
                const int ktn = (kt + 1) & 15;
#pragma unroll
                for (int nt = 0; nt < 2; nt++)
                    bvn[nt] = g_Wfh[((nbase + nt) * 16 + ktn) * 32 + lane];

                const int kb = kt * 16 + 2 * qid;
                uint32_t a[4][4];
#pragma unroll
                for (int mt = 0; mt < 4; mt++) {
                    const __nv_bfloat16* hb = hcur + (mt * 16 + gid) * HSTRH;
                    a[mt][0] = *(const uint32_t*)(hb + kb);
                    a[mt][1] = *(const uint32_t*)(hb + 8 * HSTRH + kb);
                    a[mt][2] = *(const uint32_t*)(hb + kb + 8);
                    a[mt][3] = *(const uint32_t*)(hb + 8 * HSTRH + kb + 8);
                }
#pragma unroll
                for (int nt = 0; nt < 2; nt++)
#pragma unroll
                    for (int mt = 0; mt < 4; mt++)
                        mma_bf16(cacc[nt][mt], a[mt], (const uint32_t*)&bv[nt]);
#pragma unroll
                for (int nt = 0; nt < 2; nt++) bv[nt] = bvn[nt];
            }

            // pointwise LSTM for this quarter's 2 ntiles x 4 m-tiles
#pragma unroll
            for (int nt = 0; nt < 2; nt++) {
                const int ni = q4 * 2 + nt;
                const int j  = (w * 8 + ni) * 2 + (qid >> 1);
#pragma unroll
                for (int mt = 0; mt < 4; mt++) {
                    float* C = cacc[nt][mt];
                    float sx = (qid & 1) ? C[0] : C[2];
                    float sy = (qid & 1) ? C[1] : C[3];
                    float rx = __shfl_xor_sync(0xffffffffu, sx, 1);
                    float ry = __shfl_xor_sync(0xffffffffu, sy, 1);
                    float gi, gf, gg, go;
                    if (qid & 1) { gi = rx;   gf = ry;   gg = C[2]; go = C[3]; }
                    else         { gi = C[0]; gf = C[1]; gg = rx;   go = ry;  }

                    float hh = 0.f;
                    if (act[mt]) {
                        uint2 raw = *(const uint2*)(xr[mt] + 4 * j);
                        float2 x01 = __half22float2(*(const __half2*)&raw.x);
                        float2 x23 = __half22float2(*(const __half2*)&raw.y);
                        float vi = x01.x + keep[mt] * gi;
                        float vf = x01.y + keep[mt] * gf;
                        float vg = x23.x + keep[mt] * gg;
                        float vo = x23.y + keep[mt] * go;
                        float cc = sigf(vf) * (cell[ni][mt] * keep[mt]) + sigf(vi) * tanha(vg);
                        hh = sigf(vo) * tanha(cc);
                        cell[ni][mt] = cc;
                        prj[mt] += wp8[ni] * hh;
                    }
                    hnxt[(mt * 16 + sb0) * HSTRH + j] = __float2bfloat16(hh);
                }
            }
        }

        // projection partials (qid ^ 2 shares the same stream)
#pragma unroll
        for (int mt = 0; mt < 4; mt++)
            prj[mt] += __shfl_xor_sync(0xffffffffu, prj[mt], 2);
        if (qid < 2) {
#pragma unroll
            for (int mt = 0; mt < 4; mt++)
                red[(size_t)rb * SPB_ * 16 + (mt * 16 + sb0) * 16 + w] = prj[mt];
        }
        __syncthreads();

        if (tid < SPB_) {
            int t = s_start[tid] + r;
            if (t < s_end[tid]) {
                float sum = bpv;
#pragma unroll
                for (int i = 0; i < 16; i++)
                    sum += red[(size_t)rb * SPB_ * 16 + tid * 16 + i];
                out[t * B_ + s_b[tid]] = sum;
            }
        }
        // no trailing sync: red double-buffered by rb, h by rb^1
    }
}

// ---------------- launch ----------------------------------------------------
extern "C" void kernel_launch(void* const* d_in, const int* in_sizes, int n_in,
                              void* d_out, int out_size) {
    const float* x     = (const float*)d_in[0];
    const int*   reset = (const int*)  d_in[1];
    const float* Wih   = (const float*)d_in[2];
    const float* Whh   = (const float*)d_in[3];
    const float* bih   = (const float*)d_in[4];
    const float* bhh   = (const float*)d_in[5];
    const float* Wp    = (const float*)d_in[6];
    const float* bp    = (const float*)d_in[7];
    float* out = (float*)d_out;

    const int rsm = 2 * HBUFH * 2 + 2 * SPB_ * 16 * 4 + 3 * SPB_ * 4 + 128;
    static int attr_set = 0;
    if (!attr_set) {
        cudaFuncSetAttribute(k_recur,
                             cudaFuncAttributeMaxDynamicSharedMemorySize, rsm);
        attr_set = 1;
    }

    k_bounds<<<B_, 320>>>(reset);
    k_prep<<<2048, 256>>>(Wih, Whh, bih, bhh);

    dim3 grid(G4_ / GBN, (T_ * B_) / GBM);
    k_gemm_f16<<<grid, 256>>>(x);

    k_recur<<<NBLK_, 512, rsm>>>(reset, Wp, bp, out);
}